// round 1
// baseline (speedup 1.0000x reference)
#include <cuda_runtime.h>
#include <cuda_bf16.h>
#include <cstdint>

// PaiNN conv: ds (N,64), dv (N,3,64) outputs concatenated in d_out.
// Inputs (metadata order):
// 0 node (N,64) f32
// 1 equivariant (N,3,64) f32
// 2 rbf (E,20) f32
// 3 envelope (E,1) f32
// 4 r_ij (E,3) f32
// 5 edge_index (E,2) int64 or int32 (detected at runtime)
// 6 Ws (64,64), 7 bs (64), 8 Wphi (192,64), 9 bphi (192), 10 Ww (192,20), 11 bw (192)

#define U 64
#define S3 192
#define R 20
#define MAXN 50000
#define TILE 16
#define EBLOCK 384
#define NPB 8

__device__ float g_s[(size_t)MAXN * S3];   // MLP output per node (50000 x 192)
__device__ int   g_idx_is64;

// ---------------------------------------------------------------------------
// dtype detector: int64 little-endian -> every odd 32-bit word is a high word
// (all indices < 50000, positive) -> OR of odd words == 0.
// int32 data -> odd words are real node indices, w.h.p. nonzero.
// ---------------------------------------------------------------------------
__global__ void detect_idx_kernel(const int* __restrict__ eidx32, int n_edges) {
    __shared__ int warp_or[8];
    int v = 0;
    int limit = n_edges < 4096 ? n_edges : 4096;
    for (int k = threadIdx.x; k < limit; k += blockDim.x)
        v |= eidx32[2 * k + 1];
    for (int o = 16; o > 0; o >>= 1)
        v |= __shfl_xor_sync(0xffffffffu, v, o);
    if ((threadIdx.x & 31) == 0) warp_or[threadIdx.x >> 5] = v;
    __syncthreads();
    if (threadIdx.x == 0) {
        int r = 0;
        for (int w = 0; w < (int)(blockDim.x >> 5); w++) r |= warp_or[w];
        g_idx_is64 = (r == 0) ? 1 : 0;
    }
}

// ---------------------------------------------------------------------------
// zero the output buffer
// ---------------------------------------------------------------------------
__global__ void zero_kernel(float* __restrict__ out, long long n) {
    long long n4 = n >> 2;
    float4 z = make_float4(0.f, 0.f, 0.f, 0.f);
    float4* o4 = (float4*)out;
    for (long long i = (long long)blockIdx.x * blockDim.x + threadIdx.x; i < n4;
         i += (long long)gridDim.x * blockDim.x)
        o4[i] = z;
    // scalar tail
    long long base = n4 << 2;
    for (long long i = base + (long long)blockIdx.x * blockDim.x + threadIdx.x; i < n;
         i += (long long)gridDim.x * blockDim.x)
        out[i] = 0.f;
}

// ---------------------------------------------------------------------------
// node MLP: s = silu(node@Ws^T + bs) @ Wphi^T + bphi   ->  g_s (N,192)
// weights staged in shared (padded rows of 68 floats -> conflict-free float4)
// ---------------------------------------------------------------------------
#define WPAD 68
#define SMEM_MLP ((64 * WPAD + 192 * WPAD + 64 + 192 + NPB * 64 + NPB * 64) * 4)

__global__ void mlp_kernel(const float* __restrict__ node,
                           const float* __restrict__ Ws, const float* __restrict__ bs,
                           const float* __restrict__ Wphi, const float* __restrict__ bphi,
                           int n_nodes) {
    extern __shared__ float sh[];
    float* sWs   = sh;                       // 64*68
    float* sWphi = sWs + 64 * WPAD;          // 192*68
    float* sbs   = sWphi + 192 * WPAD;       // 64
    float* sbphi = sbs + 64;                 // 192
    float* snode = sbphi + 192;              // NPB*64
    float* shh   = snode + NPB * 64;         // NPB*64

    for (int x = threadIdx.x; x < 64 * 64; x += blockDim.x)
        sWs[(x >> 6) * WPAD + (x & 63)] = Ws[x];
    for (int x = threadIdx.x; x < 192 * 64; x += blockDim.x)
        sWphi[(x >> 6) * WPAD + (x & 63)] = Wphi[x];
    for (int x = threadIdx.x; x < 64; x += blockDim.x)  sbs[x] = bs[x];
    for (int x = threadIdx.x; x < 192; x += blockDim.x) sbphi[x] = bphi[x];
    __syncthreads();

    int ngroups = (n_nodes + NPB - 1) / NPB;
    for (int g = blockIdx.x; g < ngroups; g += gridDim.x) {
        int n0 = g * NPB;
        __syncthreads();  // protect snode/shh reuse
        for (int x = threadIdx.x; x < NPB * 64; x += blockDim.x) {
            int n = x >> 6, k = x & 63;
            snode[x] = (n0 + n < n_nodes) ? node[(size_t)(n0 + n) * 64 + k] : 0.f;
        }
        __syncthreads();
        // phase 1: h = silu(node @ Ws^T + bs)
        for (int t = threadIdx.x; t < NPB * 64; t += blockDim.x) {
            int n = t >> 6, cc = t & 63;
            float acc = sbs[cc];
            const float* wrow = &sWs[cc * WPAD];
            const float* nrow = &snode[n * 64];
#pragma unroll
            for (int k = 0; k < 64; k += 4) {
                float4 wv = *(const float4*)&wrow[k];
                float4 nv = *(const float4*)&nrow[k];
                acc = fmaf(wv.x, nv.x, acc);
                acc = fmaf(wv.y, nv.y, acc);
                acc = fmaf(wv.z, nv.z, acc);
                acc = fmaf(wv.w, nv.w, acc);
            }
            float sg = 1.f / (1.f + __expf(-acc));
            shh[t] = acc * sg;
        }
        __syncthreads();
        // phase 2: s = h @ Wphi^T + bphi
        for (int t = threadIdx.x; t < NPB * S3; t += blockDim.x) {
            int n = t / S3, cc = t % S3;
            float acc = sbphi[cc];
            const float* wrow = &sWphi[cc * WPAD];
            const float* hrow = &shh[n * 64];
#pragma unroll
            for (int k = 0; k < 64; k += 4) {
                float4 wv = *(const float4*)&wrow[k];
                float4 hv = *(const float4*)&hrow[k];
                acc = fmaf(wv.x, hv.x, acc);
                acc = fmaf(wv.y, hv.y, acc);
                acc = fmaf(wv.z, hv.z, acc);
                acc = fmaf(wv.w, hv.w, acc);
            }
            if (n0 + n < n_nodes)
                g_s[(size_t)(n0 + n) * S3 + cc] = acc;
        }
    }
}

// ---------------------------------------------------------------------------
// vector red helper
// ---------------------------------------------------------------------------
__device__ __forceinline__ void red_add_v4(float* p, float4 v) {
    asm volatile("red.global.add.v4.f32 [%0], {%1, %2, %3, %4};"
                 :: "l"(p), "f"(v.x), "f"(v.y), "f"(v.z), "f"(v.w)
                 : "memory");
}

// ---------------------------------------------------------------------------
// edge kernel: tiles of 16 edges.
//  phase A: stage rbf/env/r_ij/idx in shared
//  phase B: each thread owns channel c = tid%192 (Ww row in REGISTERS),
//           computes sw[c] = s[j][c] * (rbf . Ww[c] + bw[c]) * env  -> shared
//  phase C: 64 float4 chunks per edge -> red.global.add.v4.f32
// ---------------------------------------------------------------------------
__global__ void __launch_bounds__(EBLOCK)
edge_kernel(const float* __restrict__ rbf, const float* __restrict__ env,
            const float* __restrict__ rij, const void* __restrict__ eidx,
            const float* __restrict__ Ww, const float* __restrict__ bw,
            const float* __restrict__ equiv,
            float* __restrict__ out_ds, float* __restrict__ out_dv,
            int n_edges) {
    __shared__ __align__(16) float sh_rbf[TILE][R];
    __shared__ float sh_env[TILE];
    __shared__ float sh_rij[TILE][3];
    __shared__ int   sh_i[TILE];
    __shared__ int   sh_j[TILE];
    __shared__ __align__(16) float sh_sw[TILE][S3];

    const int tid = threadIdx.x;
    const int c = tid % S3;     // owned channel
    const int p = tid / S3;     // edge parity (0/1)

    // Ww row into registers, reused for every edge
    float wwr[R];
#pragma unroll
    for (int k = 0; k < R; k++) wwr[k] = Ww[c * R + k];
    const float bwr = bw[c];
    const bool is64 = (g_idx_is64 != 0);

    int ntiles = (n_edges + TILE - 1) / TILE;
    for (int tile = blockIdx.x; tile < ntiles; tile += gridDim.x) {
        int e0 = tile * TILE;
        __syncthreads();  // prev phase C done before overwriting shared

        // ---- phase A: stage tile ----
        if (tid < TILE * R) {
            int e = tid / R, k = tid % R;
            sh_rbf[e][k] = (e0 + e < n_edges) ? rbf[(size_t)(e0 + e) * R + k] : 0.f;
        } else if (tid < TILE * R + TILE) {
            int e = tid - TILE * R;
            sh_env[e] = (e0 + e < n_edges) ? env[e0 + e] : 0.f;
        } else if (tid < TILE * R + 2 * TILE) {
            int e = tid - (TILE * R + TILE);
            int ge = e0 + e;
            int iv = -1, jv = 0;
            if (ge < n_edges) {
                if (is64) {
                    const long long* pp = (const long long*)eidx;
                    iv = (int)pp[2 * (size_t)ge];
                    jv = (int)pp[2 * (size_t)ge + 1];
                } else {
                    const int* pp = (const int*)eidx;
                    iv = pp[2 * (size_t)ge];
                    jv = pp[2 * (size_t)ge + 1];
                }
            }
            sh_i[e] = iv;
            sh_j[e] = jv;
        } else {
            for (int x = tid - (TILE * R + 2 * TILE); x < TILE * 3; x += EBLOCK - (TILE * R + 2 * TILE)) {
                int e = x / 3, d = x % 3;
                sh_rij[e][d] = (e0 + e < n_edges) ? rij[(size_t)(e0 + e) * 3 + d] : 0.f;
            }
        }
        __syncthreads();

        // ---- phase B: sw = s[j] * w ----
        for (int el = p; el < TILE; el += 2) {
            float rb[R];
#pragma unroll
            for (int kk = 0; kk < R / 4; kk++) {
                float4 t4 = *(const float4*)&sh_rbf[el][kk * 4];
                rb[kk * 4 + 0] = t4.x; rb[kk * 4 + 1] = t4.y;
                rb[kk * 4 + 2] = t4.z; rb[kk * 4 + 3] = t4.w;
            }
            float acc = bwr;
#pragma unroll
            for (int k = 0; k < R; k++) acc = fmaf(rb[k], wwr[k], acc);
            float w = acc * sh_env[el];
            int j = sh_j[el];
            float sval = g_s[(size_t)j * S3 + c];  // coalesced: warp = consec. c
            sh_sw[el][c] = sval * w;
        }
        __syncthreads();

        // ---- phase C: scatter 64 float4 chunks per edge ----
        for (int task = tid; task < TILE * 64; task += EBLOCK) {
            int e = task >> 6;
            int q = task & 63;
            int i = sh_i[e];
            if (i < 0) continue;
            if (q < 16) {
                const float* sp = &sh_sw[e][q * 4];
                float4 v = *(const float4*)sp;
                red_add_v4(out_ds + (size_t)i * 64 + q * 4, v);
            } else {
                int x = q - 16;
                int d = x >> 4;
                int c4 = (x & 15) * 4;
                int j = sh_j[e];
                float4 s2 = *(const float4*)&sh_sw[e][64 + c4];
                float4 s3 = *(const float4*)&sh_sw[e][128 + c4];
                float4 vj = *(const float4*)&equiv[((size_t)j * 3 + d) * 64 + c4];
                float rd = sh_rij[e][d];
                float4 v;
                v.x = fmaf(rd, s3.x, vj.x * s2.x);
                v.y = fmaf(rd, s3.y, vj.y * s2.y);
                v.z = fmaf(rd, s3.z, vj.z * s2.z);
                v.w = fmaf(rd, s3.w, vj.w * s2.w);
                red_add_v4(out_dv + ((size_t)i * 3 + d) * 64 + c4, v);
            }
        }
    }
}

// ---------------------------------------------------------------------------
extern "C" void kernel_launch(void* const* d_in, const int* in_sizes, int n_in,
                              void* d_out, int out_size) {
    const float* node  = (const float*)d_in[0];
    const float* equiv = (const float*)d_in[1];
    const float* rbf   = (const float*)d_in[2];
    const float* env   = (const float*)d_in[3];
    const float* rij   = (const float*)d_in[4];
    const void*  eidx  = d_in[5];
    const float* Ws    = (const float*)d_in[6];
    const float* bs    = (const float*)d_in[7];
    const float* Wphi  = (const float*)d_in[8];
    const float* bphi  = (const float*)d_in[9];
    const float* Ww    = (const float*)d_in[10];
    const float* bw    = (const float*)d_in[11];

    int n_nodes = in_sizes[0] / U;
    int n_edges = in_sizes[3];

    float* out_ds = (float*)d_out;
    float* out_dv = out_ds + (size_t)n_nodes * U;

    detect_idx_kernel<<<1, 256>>>((const int*)eidx, n_edges);
    zero_kernel<<<592, 256>>>((float*)d_out, (long long)out_size);

    cudaFuncSetAttribute(mlp_kernel, cudaFuncAttributeMaxDynamicSharedMemorySize, SMEM_MLP);
    mlp_kernel<<<592, 256, SMEM_MLP>>>(node, Ws, bs, Wphi, bphi, n_nodes);

    edge_kernel<<<592, EBLOCK>>>(rbf, env, rij, eidx, Ww, bw, equiv,
                                 out_ds, out_dv, n_edges);
}

// round 2
// speedup vs baseline: 1.3333x; 1.3333x over previous
#include <cuda_runtime.h>
#include <cuda_bf16.h>
#include <cstdint>

// PaiNN conv: ds (N,64), dv (N,3,64) concatenated in d_out.
// Inputs: 0 node(N,64) 1 equivariant(N,3,64) 2 rbf(E,20) 3 envelope(E,1)
//         4 r_ij(E,3) 5 edge_index(E,2) i64/i32  6 Ws(64,64) 7 bs(64)
//         8 Wphi(192,64) 9 bphi(192) 10 Ww(192,20) 11 bw(192)

#define U 64
#define S3 192
#define R 20
#define MAXN 50000
#define MAXE 800000
#define NPB 8
#define CH 16

__device__ float g_s[(size_t)MAXN * S3];
__device__ int   g_idx_is64;
__device__ int   g_cnt[MAXN];
__device__ int   g_scan[MAXN];
__device__ int   g_bsum[64];
__device__ int   g_off[MAXN + 1];
__device__ int   g_run[MAXN];
__device__ int2  g_perm[MAXE];

// ---------------- packed f32x2 helpers ----------------
__device__ __forceinline__ unsigned long long pk2(float lo, float hi) {
    unsigned long long r;
    asm("mov.b64 %0, {%1, %2};" : "=l"(r) : "f"(lo), "f"(hi));
    return r;
}
__device__ __forceinline__ unsigned long long fma2(unsigned long long a,
                                                   unsigned long long b,
                                                   unsigned long long c) {
    unsigned long long d;
    asm("fma.rn.f32x2 %0, %1, %2, %3;" : "=l"(d) : "l"(a), "l"(b), "l"(c));
    return d;
}
__device__ __forceinline__ float upk_sum(unsigned long long a) {
    float lo, hi;
    asm("mov.b64 {%0, %1}, %2;" : "=f"(lo), "=f"(hi) : "l"(a));
    return lo + hi;
}

// ---------------- idx dtype detector ----------------
__global__ void detect_idx_kernel(const int* __restrict__ eidx32, int n_edges) {
    __shared__ int warp_or[8];
    int v = 0;
    int limit = n_edges < 4096 ? n_edges : 4096;
    for (int k = threadIdx.x; k < limit; k += blockDim.x)
        v |= eidx32[2 * k + 1];
    for (int o = 16; o > 0; o >>= 1)
        v |= __shfl_xor_sync(0xffffffffu, v, o);
    if ((threadIdx.x & 31) == 0) warp_or[threadIdx.x >> 5] = v;
    __syncthreads();
    if (threadIdx.x == 0) {
        int r = 0;
        for (int w = 0; w < (int)(blockDim.x >> 5); w++) r |= warp_or[w];
        g_idx_is64 = (r == 0) ? 1 : 0;
    }
}

// ---------------- zero the per-node counters ----------------
__global__ void zero_cnt_kernel(int n_nodes) {
    int i = blockIdx.x * blockDim.x + threadIdx.x;
    if (i < n_nodes) g_cnt[i] = 0;
}

// ---------------- histogram over dst ----------------
__global__ void hist_kernel(const void* __restrict__ eidx, int n_edges) {
    const bool is64 = (g_idx_is64 != 0);
    for (int e = blockIdx.x * blockDim.x + threadIdx.x; e < n_edges;
         e += gridDim.x * blockDim.x) {
        int dst = is64 ? (int)((const long long*)eidx)[2 * (size_t)e]
                       : ((const int*)eidx)[2 * (size_t)e];
        atomicAdd(&g_cnt[dst], 1);
    }
}

// ---------------- 2-level exclusive scan ----------------
__global__ void scan1_kernel(int n_nodes) {
    __shared__ int sh[1024];
    int tid = threadIdx.x;
    int i = blockIdx.x * 1024 + tid;
    int v = (i < n_nodes) ? g_cnt[i] : 0;
    sh[tid] = v;
    __syncthreads();
    for (int off = 1; off < 1024; off <<= 1) {
        int t = (tid >= off) ? sh[tid - off] : 0;
        __syncthreads();
        sh[tid] += t;
        __syncthreads();
    }
    if (i < n_nodes) g_scan[i] = sh[tid] - v;  // exclusive within block
    if (tid == 1023) g_bsum[blockIdx.x] = sh[1023];
}

__global__ void scan2_kernel(int nb) {
    if (threadIdx.x == 0 && blockIdx.x == 0) {
        int s = 0;
        for (int b = 0; b < nb; b++) {
            int t = g_bsum[b];
            g_bsum[b] = s;
            s += t;
        }
    }
}

__global__ void scan3_kernel(int n_nodes, int n_edges) {
    int i = blockIdx.x * blockDim.x + threadIdx.x;
    if (i < n_nodes) {
        int off = g_scan[i] + g_bsum[i >> 10];
        g_off[i] = off;
        g_run[i] = off;
    }
    if (i == 0) g_off[n_nodes] = n_edges;
}

// ---------------- scatter: build permutation (e, j) sorted by dst ----------------
__global__ void scatter_kernel(const void* __restrict__ eidx, int n_edges) {
    const bool is64 = (g_idx_is64 != 0);
    for (int e = blockIdx.x * blockDim.x + threadIdx.x; e < n_edges;
         e += gridDim.x * blockDim.x) {
        int dst, j;
        if (is64) {
            const long long* p = (const long long*)eidx;
            dst = (int)p[2 * (size_t)e];
            j = (int)p[2 * (size_t)e + 1];
        } else {
            const int* p = (const int*)eidx;
            dst = p[2 * (size_t)e];
            j = p[2 * (size_t)e + 1];
        }
        int pos = atomicAdd(&g_run[dst], 1);
        g_perm[pos] = make_int2(e, j);
    }
}

// ---------------- node MLP (f32x2 inner product) ----------------
#define WPAD 68
#define SMEM_MLP ((64 * WPAD + 192 * WPAD + 64 + 192 + NPB * 64 + NPB * 64) * 4)

__global__ void mlp_kernel(const float* __restrict__ node,
                           const float* __restrict__ Ws, const float* __restrict__ bs,
                           const float* __restrict__ Wphi, const float* __restrict__ bphi,
                           int n_nodes) {
    extern __shared__ float sh[];
    float* sWs   = sh;
    float* sWphi = sWs + 64 * WPAD;
    float* sbs   = sWphi + 192 * WPAD;
    float* sbphi = sbs + 64;
    float* snode = sbphi + 192;
    float* shh   = snode + NPB * 64;

    for (int x = threadIdx.x; x < 64 * 64; x += blockDim.x)
        sWs[(x >> 6) * WPAD + (x & 63)] = Ws[x];
    for (int x = threadIdx.x; x < 192 * 64; x += blockDim.x)
        sWphi[(x >> 6) * WPAD + (x & 63)] = Wphi[x];
    for (int x = threadIdx.x; x < 64; x += blockDim.x)  sbs[x] = bs[x];
    for (int x = threadIdx.x; x < 192; x += blockDim.x) sbphi[x] = bphi[x];
    __syncthreads();

    int ngroups = (n_nodes + NPB - 1) / NPB;
    for (int g = blockIdx.x; g < ngroups; g += gridDim.x) {
        int n0 = g * NPB;
        __syncthreads();
        for (int x = threadIdx.x; x < NPB * 64; x += blockDim.x) {
            int n = x >> 6, k = x & 63;
            snode[x] = (n0 + n < n_nodes) ? node[(size_t)(n0 + n) * 64 + k] : 0.f;
        }
        __syncthreads();
        for (int t = threadIdx.x; t < NPB * 64; t += blockDim.x) {
            int n = t >> 6, cc = t & 63;
            const ulonglong2* wp = (const ulonglong2*)&sWs[cc * WPAD];
            const ulonglong2* np = (const ulonglong2*)&snode[n * 64];
            unsigned long long acc = pk2(sbs[cc], 0.f);
#pragma unroll
            for (int q = 0; q < 16; q++) {
                ulonglong2 a = wp[q];
                ulonglong2 b = np[q];
                acc = fma2(a.x, b.x, acc);
                acc = fma2(a.y, b.y, acc);
            }
            float v = upk_sum(acc);
            float sg = 1.f / (1.f + __expf(-v));
            shh[t] = v * sg;
        }
        __syncthreads();
        for (int t = threadIdx.x; t < NPB * S3; t += blockDim.x) {
            int n = t / S3, cc = t % S3;
            const ulonglong2* wp = (const ulonglong2*)&sWphi[cc * WPAD];
            const ulonglong2* hp = (const ulonglong2*)&shh[n * 64];
            unsigned long long acc = pk2(sbphi[cc], 0.f);
#pragma unroll
            for (int q = 0; q < 16; q++) {
                ulonglong2 a = wp[q];
                ulonglong2 b = hp[q];
                acc = fma2(a.x, b.x, acc);
                acc = fma2(a.y, b.y, acc);
            }
            if (n0 + n < n_nodes)
                g_s[(size_t)(n0 + n) * S3 + cc] = upk_sum(acc);
        }
    }
}

// ---------------- node-centric edge aggregation (no atomics) ----------------
__global__ void __launch_bounds__(64, 8)
node_kernel(const float* __restrict__ rbf, const float* __restrict__ env,
            const float* __restrict__ rij,
            const float* __restrict__ Ww, const float* __restrict__ bw,
            const float* __restrict__ equiv,
            float* __restrict__ out_ds, float* __restrict__ out_dv,
            int n_nodes) {
    __shared__ __align__(16) float sh_rbf[CH][R];
    __shared__ float sh_env[CH];
    __shared__ float sh_rij[CH][3];
    __shared__ int   sh_e[CH];
    __shared__ int   sh_j[CH];

    const int c = threadIdx.x;  // owned channel 0..63

    // Ww rows for channels c, 64+c, 128+c packed into f32x2 registers
    unsigned long long wwp[3][10];
    float bwv[3];
#pragma unroll
    for (int g = 0; g < 3; g++) {
        const float* wr = Ww + (size_t)(g * 64 + c) * R;
#pragma unroll
        for (int k = 0; k < 10; k++)
            wwp[g][k] = pk2(wr[2 * k], wr[2 * k + 1]);
        bwv[g] = bw[g * 64 + c];
    }

    for (int i = blockIdx.x; i < n_nodes; i += gridDim.x) {
        int start = g_off[i], end = g_off[i + 1];
        float ds_acc = 0.f;
        float dv0 = 0.f, dv1 = 0.f, dv2 = 0.f;

        for (int base = start; base < end; base += CH) {
            int cnt = min(CH, end - base);
            __syncthreads();  // shared reuse guard
            if (c < cnt) {
                int2 ej = g_perm[base + c];
                int e = ej.x;
                sh_e[c] = e;
                sh_j[c] = ej.y;
                sh_env[c] = env[e];
                sh_rij[c][0] = rij[3 * (size_t)e];
                sh_rij[c][1] = rij[3 * (size_t)e + 1];
                sh_rij[c][2] = rij[3 * (size_t)e + 2];
            }
            __syncthreads();
            for (int x = c; x < cnt * R; x += 64) {
                int el = x / R, k = x % R;
                sh_rbf[el][k] = rbf[(size_t)sh_e[el] * R + k];
            }
            __syncthreads();

            for (int el = 0; el < cnt; el++) {
                int j = sh_j[el];
                // gathers issued first to overlap with the dot products
                const float* sp = g_s + (size_t)j * S3 + c;
                float s0 = sp[0], s1 = sp[64], s2v = sp[128];
                const float* vp = equiv + (size_t)j * S3 + c;
                float v0 = vp[0], v1 = vp[64], v2 = vp[128];
                float en = sh_env[el];
                float r0 = sh_rij[el][0], r1 = sh_rij[el][1], r2 = sh_rij[el][2];

                unsigned long long rbp[10];
                const float4* rb4 = (const float4*)sh_rbf[el];
#pragma unroll
                for (int q = 0; q < 5; q++) {
                    float4 t = rb4[q];
                    rbp[2 * q]     = pk2(t.x, t.y);
                    rbp[2 * q + 1] = pk2(t.z, t.w);
                }
                float w[3];
#pragma unroll
                for (int g = 0; g < 3; g++) {
                    unsigned long long acc = pk2(bwv[g], 0.f);
#pragma unroll
                    for (int k = 0; k < 10; k++)
                        acc = fma2(rbp[k], wwp[g][k], acc);
                    w[g] = upk_sum(acc) * en;
                }
                float sw0 = s0 * w[0];
                float sw1 = s1 * w[1];
                float sw2 = s2v * w[2];
                ds_acc += sw0;
                dv0 = fmaf(v0, sw1, fmaf(r0, sw2, dv0));
                dv1 = fmaf(v1, sw1, fmaf(r1, sw2, dv1));
                dv2 = fmaf(v2, sw1, fmaf(r2, sw2, dv2));
            }
        }
        out_ds[(size_t)i * U + c] = ds_acc;
        out_dv[((size_t)i * 3 + 0) * U + c] = dv0;
        out_dv[((size_t)i * 3 + 1) * U + c] = dv1;
        out_dv[((size_t)i * 3 + 2) * U + c] = dv2;
    }
}

// ---------------------------------------------------------------------------
extern "C" void kernel_launch(void* const* d_in, const int* in_sizes, int n_in,
                              void* d_out, int out_size) {
    const float* node  = (const float*)d_in[0];
    const float* equiv = (const float*)d_in[1];
    const float* rbf   = (const float*)d_in[2];
    const float* env   = (const float*)d_in[3];
    const float* rij   = (const float*)d_in[4];
    const void*  eidx  = d_in[5];
    const float* Ws    = (const float*)d_in[6];
    const float* bs    = (const float*)d_in[7];
    const float* Wphi  = (const float*)d_in[8];
    const float* bphi  = (const float*)d_in[9];
    const float* Ww    = (const float*)d_in[10];
    const float* bw    = (const float*)d_in[11];

    int n_nodes = in_sizes[0] / U;
    int n_edges = in_sizes[3];

    float* out_ds = (float*)d_out;
    float* out_dv = out_ds + (size_t)n_nodes * U;

    int nb_scan = (n_nodes + 1023) / 1024;

    detect_idx_kernel<<<1, 256>>>((const int*)eidx, n_edges);
    zero_cnt_kernel<<<(n_nodes + 255) / 256, 256>>>(n_nodes);

    cudaFuncSetAttribute(mlp_kernel, cudaFuncAttributeMaxDynamicSharedMemorySize, SMEM_MLP);
    mlp_kernel<<<592, 256, SMEM_MLP>>>(node, Ws, bs, Wphi, bphi, n_nodes);

    hist_kernel<<<400, 256>>>(eidx, n_edges);
    scan1_kernel<<<nb_scan, 1024>>>(n_nodes);
    scan2_kernel<<<1, 32>>>(nb_scan);
    scan3_kernel<<<(n_nodes + 1023) / 1024, 1024>>>(n_nodes, n_edges);
    scatter_kernel<<<400, 256>>>(eidx, n_edges);

    node_kernel<<<1480, 64>>>(rbf, env, rij, Ww, bw, equiv,
                              out_ds, out_dv, n_nodes);
}